// round 10
// baseline (speedup 1.0000x reference)
#include <cuda_runtime.h>
#include <cuda_bf16.h>
#include <cstdint>

// Problem constants (match reference)
#define Nn 50000
#define Ee 640000
#define Hh 128
#define Gg 64
#define Oo 16

#define SCAN_B 512
#define SCAN_NB ((Nn + SCAN_B - 1) / SCAN_B)   // 98

// Scratch (static __device__ — no allocs allowed)
__device__ float g_deg[Nn];
__device__ float g_dinv[Nn];
__device__ float g_xw[(size_t)Nn * Hh];
__device__ float g_h[(size_t)Nn * Hh];
__device__ float g_pool[Gg * Hh];
__device__ float g_cnt[Gg];

// CSR scratch
__device__ int    g_count[Nn];
__device__ int    g_cursor[Nn];
__device__ int    g_scan[Nn];
__device__ int    g_bsum[SCAN_NB];
__device__ int    g_boff[SCAN_NB];
__device__ int    g_rowptr[Nn + 1];
__device__ float2 g_csr[Ee];        // .x = src index (int bits), .y = coef

// ---------------- helpers ----------------

__device__ __forceinline__ uint32_t smem_u32(const void* p) {
    uint32_t a;
    asm("{ .reg .u64 t; cvta.to.shared.u64 t, %1; cvt.u32.u64 %0, t; }"
        : "=r"(a) : "l"(p));
    return a;
}

#define LDMATRIX_X4(r0, r1, r2, r3, addr) \
    asm volatile("ldmatrix.sync.aligned.m8n8.x4.shared.b16 {%0,%1,%2,%3}, [%4];" \
                 : "=r"(r0), "=r"(r1), "=r"(r2), "=r"(r3) : "r"(addr))

#define MMA_BF16(c, a0, a1, a2, a3, b0, b1) \
    asm volatile("mma.sync.aligned.m16n8k16.row.col.f32.bf16.bf16.f32 " \
                 "{%0,%1,%2,%3}, {%4,%5,%6,%7}, {%8,%9}, {%0,%1,%2,%3};" \
                 : "+f"((c)[0]), "+f"((c)[1]), "+f"((c)[2]), "+f"((c)[3]) \
                 : "r"(a0), "r"(a1), "r"(a2), "r"(a3), "r"(b0), "r"(b1))

__device__ __forceinline__ uint32_t pack_bf16x2(__nv_bfloat16 lo, __nv_bfloat16 hi) {
    __nv_bfloat162 p(lo, hi);
    return *(uint32_t*)&p;
}

// ---------------- tensor-core GEMM via mma.sync (baseline PTX) -------------
// g_xw[n,128] = src[n,128] @ W[128,128]; src = A or g_h when A==nullptr.
// bf16 split x = hi + lo; acc = hi*Whi + hi*Wlo + lo*Whi (fp32 accum).
// Block tile 128x128, 8 warps, warp = 16 rows x 128 cols.
// Smem: A row-major [row][k], B n-major [nn][k] (B[nn][k] = W[k][nn]),
// row stride 136 bf16 = 272 B (16B-aligned; rows advance 4 banks ->
// conflict-free ldmatrix).

#define TSTRIDE 136
#define TILE_BYTES (128 * TSTRIDE * 2)   // 34816
#define SM_AH 0
#define SM_AL (SM_AH + TILE_BYTES)
#define SM_BH (SM_AL + TILE_BYTES)
#define SM_BL (SM_BH + TILE_BYTES)
#define SM_GEMM_TOTAL (SM_BL + TILE_BYTES)   // 139264

__global__ void __launch_bounds__(256, 1)
gemm_mma_kernel(const float* __restrict__ A, const float* __restrict__ W, int n) {
    extern __shared__ char smem[];
    const float* src = A ? A : (const float*)g_h;
    const uint32_t sb = smem_u32(smem);
    const int tid = threadIdx.x;
    const int wid = tid >> 5;
    const int lid = tid & 31;
    const int block_row = blockIdx.x * 128;

    // ---- fill A tile (hi/lo bf16) ----
    for (int i = tid; i < 4096; i += 256) {        // 4096 float4 = 128x128 fp32
        int r = i >> 5;
        int cq = i & 31;
        int c = cq * 4;
        int gr = block_row + r;
        float4 v = make_float4(0.f, 0.f, 0.f, 0.f);
        if (gr < n) v = ((const float4*)src)[(size_t)gr * 32 + cq];

        __nv_bfloat16 h0 = __float2bfloat16_rn(v.x);
        __nv_bfloat16 h1 = __float2bfloat16_rn(v.y);
        __nv_bfloat16 h2 = __float2bfloat16_rn(v.z);
        __nv_bfloat16 h3 = __float2bfloat16_rn(v.w);
        __nv_bfloat16 l0 = __float2bfloat16_rn(v.x - __bfloat162float(h0));
        __nv_bfloat16 l1 = __float2bfloat16_rn(v.y - __bfloat162float(h1));
        __nv_bfloat16 l2 = __float2bfloat16_rn(v.z - __bfloat162float(h2));
        __nv_bfloat16 l3 = __float2bfloat16_rn(v.w - __bfloat162float(h3));

        uint32_t off = (uint32_t)r * (TSTRIDE * 2) + (uint32_t)c * 2;
        *(uint2*)(smem + SM_AH + off) = make_uint2(pack_bf16x2(h0, h1), pack_bf16x2(h2, h3));
        *(uint2*)(smem + SM_AL + off) = make_uint2(pack_bf16x2(l0, l1), pack_bf16x2(l2, l3));
    }

    // ---- fill B tile: Bsm[nn][k] = W[k][nn] ----
    {
        int nn = tid & 127;
        int k0 = (tid >> 7) * 64;
        uint32_t base = (uint32_t)nn * (TSTRIDE * 2);
#pragma unroll 4
        for (int k = k0; k < k0 + 64; k++) {
            float w = W[(size_t)k * 128 + nn];
            __nv_bfloat16 hw = __float2bfloat16_rn(w);
            __nv_bfloat16 lw = __float2bfloat16_rn(w - __bfloat162float(hw));
            *(__nv_bfloat16*)(smem + SM_BH + base + k * 2) = hw;
            *(__nv_bfloat16*)(smem + SM_BL + base + k * 2) = lw;
        }
    }
    __syncthreads();

    // ---- mma mainloop ----
    const int m0 = wid * 16;
    float acc[8][2][4];
#pragma unroll
    for (int np = 0; np < 8; np++)
#pragma unroll
        for (int h = 0; h < 2; h++)
#pragma unroll
            for (int j = 0; j < 4; j++) acc[np][h][j] = 0.0f;

    // per-lane ldmatrix address components
    const int lgrp = lid >> 3;
    const int lrow = lid & 7;
    // A: row = m0 + (lgrp&1)*8 + lrow; col = (lgrp>>1)*8 + k0
    const uint32_t a_row_off = (uint32_t)(m0 + ((lgrp & 1) << 3) + lrow) * (TSTRIDE * 2)
                             + (uint32_t)((lgrp >> 1) << 3) * 2;
    // B: nn = n0 + (lgrp>>1)*8 + lrow; kk = k0 + (lgrp&1)*8
    const uint32_t b_row_off = (uint32_t)(((lgrp >> 1) << 3) + lrow) * (TSTRIDE * 2)
                             + (uint32_t)((lgrp & 1) << 3) * 2;

#pragma unroll
    for (int pass = 0; pass < 3; pass++) {
        const uint32_t abase = sb + ((pass == 2) ? SM_AL : SM_AH) + a_row_off;
        const uint32_t bbase = sb + ((pass == 1) ? SM_BL : SM_BH) + b_row_off;
#pragma unroll
        for (int kc = 0; kc < 8; kc++) {
            uint32_t a0, a1, a2, a3;
            LDMATRIX_X4(a0, a1, a2, a3, abase + kc * 32);   // kc*16 cols * 2B
#pragma unroll
            for (int np = 0; np < 8; np++) {
                uint32_t b0, b1, b2, b3;
                LDMATRIX_X4(b0, b1, b2, b3,
                            bbase + (uint32_t)np * 16 * (TSTRIDE * 2) + kc * 32);
                MMA_BF16(acc[np][0], a0, a1, a2, a3, b0, b1);
                MMA_BF16(acc[np][1], a0, a1, a2, a3, b2, b3);
            }
        }
    }

    // ---- epilogue: write fp32 results ----
    {
        int r0 = block_row + m0 + (lid >> 2);
        int cb = (lid & 3) * 2;
#pragma unroll
        for (int np = 0; np < 8; np++) {
#pragma unroll
            for (int h = 0; h < 2; h++) {
                int col = np * 16 + h * 8 + cb;
                if (r0 < n)
                    *(float2*)(g_xw + (size_t)r0 * 128 + col) =
                        make_float2(acc[np][h][0], acc[np][h][1]);
                if (r0 + 8 < n)
                    *(float2*)(g_xw + (size_t)(r0 + 8) * 128 + col) =
                        make_float2(acc[np][h][2], acc[np][h][3]);
            }
        }
    }
}

// ---------------- init ----------------

__global__ void init_node_kernel() {
    int i = blockIdx.x * blockDim.x + threadIdx.x;
    if (i < Nn) {
        g_deg[i] = 1.0f;   // self-loop weight 1
        g_count[i] = 0;
        g_cursor[i] = 0;
    }
    if (i < Gg * Hh) g_pool[i] = 0.0f;
    if (i < Gg) g_cnt[i] = 0.0f;
}

__global__ void deg_count_kernel(const int* __restrict__ col,
                                 const float* __restrict__ ew) {
    int e = blockIdx.x * blockDim.x + threadIdx.x;
    if (e < Ee) {
        int c = col[e];
        atomicAdd(&g_deg[c], ew[e]);
        atomicAdd(&g_count[c], 1);
    }
}

// ---------------- scan ----------------

__global__ void scan_block_kernel() {
    __shared__ int sh[SCAN_B];
    int tid = threadIdx.x;
    int i = blockIdx.x * SCAN_B + tid;
    if (i < Nn) {
        float d = g_deg[i];
        g_dinv[i] = (d > 0.0f) ? rsqrtf(d) : 0.0f;
    }
    int v = (i < Nn) ? g_count[i] : 0;
    sh[tid] = v;
    __syncthreads();
#pragma unroll
    for (int o = 1; o < SCAN_B; o <<= 1) {
        int t = (tid >= o) ? sh[tid - o] : 0;
        __syncthreads();
        sh[tid] += t;
        __syncthreads();
    }
    if (i < Nn) g_scan[i] = sh[tid];
    if (tid == SCAN_B - 1) g_bsum[blockIdx.x] = sh[tid];
}

__global__ void scan_bsum_kernel() {
    __shared__ int sh[128];
    int tid = threadIdx.x;
    int v = (tid < SCAN_NB) ? g_bsum[tid] : 0;
    sh[tid] = v;
    __syncthreads();
#pragma unroll
    for (int o = 1; o < 128; o <<= 1) {
        int t = (tid >= o) ? sh[tid - o] : 0;
        __syncthreads();
        sh[tid] += t;
        __syncthreads();
    }
    if (tid < SCAN_NB) g_boff[tid] = sh[tid] - v;
}

__global__ void scan_final_kernel() {
    int i = blockIdx.x * blockDim.x + threadIdx.x;
    if (i < Nn) {
        g_rowptr[i + 1] = g_scan[i] + g_boff[i / SCAN_B];
        if (i == 0) g_rowptr[0] = 0;
    }
}

__global__ void csr_fill_kernel(const int* __restrict__ row,
                                const int* __restrict__ col,
                                const float* __restrict__ ew) {
    int e = blockIdx.x * blockDim.x + threadIdx.x;
    if (e >= Ee) return;
    int r = row[e];
    int c = col[e];
    int p = g_rowptr[c] + atomicAdd(&g_cursor[c], 1);
    g_csr[p] = make_float2(__int_as_float(r), g_dinv[r] * ew[e] * g_dinv[c]);
}

// ---------------- gather core: predicated x8 blocks ------------------------

__device__ __forceinline__ float4 gather_node(int node, int lane,
                                              const float* __restrict__ b) {
    const int start = g_rowptr[node];
    const int end = g_rowptr[node + 1];
    const int cnt = end - start;

    float di = g_dinv[node];
    float d2 = di * di;
    float4 sv = ((const float4*)(g_xw + (size_t)node * Hh))[lane];
    float ax = sv.x * d2, ay = sv.y * d2, az = sv.z * d2, aw = sv.w * d2;

#pragma unroll 1
    for (int blk = 0; blk < cnt; blk += 8) {
        float2 e[8];
        float cf[8];
#pragma unroll
        for (int u = 0; u < 8; u++) {
            int q = blk + u;
            int qs = (q < cnt) ? q : cnt - 1;
            e[u] = g_csr[start + qs];
            cf[u] = (q < cnt) ? e[u].y : 0.0f;
        }
        float4 v[8];
#pragma unroll
        for (int u = 0; u < 8; u++)
            v[u] = ((const float4*)(g_xw + (size_t)__float_as_int(e[u].x) * Hh))[lane];
#pragma unroll
        for (int u = 0; u < 8; u++) {
            ax += cf[u] * v[u].x;
            ay += cf[u] * v[u].y;
            az += cf[u] * v[u].z;
            aw += cf[u] * v[u].w;
        }
    }

    float4 bv = *(const float4*)(b + lane * 4);
    return make_float4(fmaxf(ax + bv.x, 0.0f), fmaxf(ay + bv.y, 0.0f),
                       fmaxf(az + bv.z, 0.0f), fmaxf(aw + bv.w, 0.0f));
}

__global__ void gather1_kernel(const float* __restrict__ b) {
    int node = blockIdx.x * 8 + (threadIdx.x >> 5);
    if (node >= Nn) return;
    int lane = threadIdx.x & 31;
    float4 acc = gather_node(node, lane, b);
    ((float4*)(g_h + (size_t)node * Hh))[lane] = acc;
}

__global__ void gather2_pool_kernel(const float* __restrict__ b,
                                    const int* __restrict__ batch) {
    int node = blockIdx.x * 8 + (threadIdx.x >> 5);
    if (node >= Nn) return;
    int lane = threadIdx.x & 31;
    float4 acc = gather_node(node, lane, b);
    int bg = batch[node];
    float* pl = g_pool + bg * Hh + lane * 4;
    atomicAdd(pl + 0, acc.x);
    atomicAdd(pl + 1, acc.y);
    atomicAdd(pl + 2, acc.z);
    atomicAdd(pl + 3, acc.w);
    if (lane == 0) atomicAdd(&g_cnt[bg], 1.0f);
}

// ---------------- final FC ----------------

__global__ void fc_kernel(float* __restrict__ out,
                          const float* __restrict__ Wfc,
                          const float* __restrict__ bfc) {
    int g = threadIdx.x >> 4;
    int o = threadIdx.x & 15;
    float inv = 1.0f / fmaxf(g_cnt[g], 1.0f);
    float acc = 0.0f;
#pragma unroll 8
    for (int k = 0; k < Hh; k++) acc += g_pool[g * Hh + k] * Wfc[k * Oo + o];
    out[g * Oo + o] = acc * inv + bfc[o];
}

// ---------------- launch ----------------

extern "C" void kernel_launch(void* const* d_in, const int* in_sizes, int n_in,
                              void* d_out, int out_size) {
    const float* x = (const float*)d_in[0];
    const int* edge_index = (const int*)d_in[1];   // int32
    const float* ew = (const float*)d_in[2];
    const int* batch = (const int*)d_in[3];        // int32
    const float* W1 = (const float*)d_in[4];
    const float* b1 = (const float*)d_in[5];
    const float* W2 = (const float*)d_in[6];
    const float* b2 = (const float*)d_in[7];
    const float* Wfc = (const float*)d_in[8];
    const float* bfc = (const float*)d_in[9];
    float* out = (float*)d_out;

    const int* row = edge_index;        // edge_index[0]
    const int* col = edge_index + Ee;   // edge_index[1]

    const int nblk = (Nn + 255) / 256;
    const int eblk = (Ee + 255) / 256;
    const int gemm_blocks = (Nn + 127) / 128;   // 391
    const int warp8_blocks = (Nn + 7) / 8;

    cudaFuncSetAttribute(gemm_mma_kernel,
                         cudaFuncAttributeMaxDynamicSharedMemorySize, SM_GEMM_TOTAL);

    // degree + CSR build
    init_node_kernel<<<nblk, 256>>>();
    deg_count_kernel<<<eblk, 256>>>(col, ew);
    scan_block_kernel<<<SCAN_NB, SCAN_B>>>();   // also computes dinv
    scan_bsum_kernel<<<1, 128>>>();
    scan_final_kernel<<<nblk, 256>>>();
    csr_fill_kernel<<<eblk, 256>>>(row, col, ew);

    // layer 1: xw = x@W1 ; h = relu(gather(xw) + dinv^2*xw + b1)
    gemm_mma_kernel<<<gemm_blocks, 256, SM_GEMM_TOTAL>>>(x, W1, Nn);
    gather1_kernel<<<warp8_blocks, 256>>>(b1);

    // layer 2: xw = h@W2 ; pooled gather (no h2 materialization)
    gemm_mma_kernel<<<gemm_blocks, 256, SM_GEMM_TOTAL>>>(nullptr, W2, Nn);
    gather2_pool_kernel<<<warp8_blocks, 256>>>(b2, batch);

    // fc
    fc_kernel<<<1, Gg * Oo>>>(out, Wfc, bfc);
}

// round 11
// speedup vs baseline: 1.1414x; 1.1414x over previous
#include <cuda_runtime.h>
#include <cuda_bf16.h>
#include <cstdint>

// Problem constants (match reference)
#define Nn 50000
#define Ee 640000
#define Hh 128
#define Gg 64
#define Oo 16

#define SCAN_B 512
#define SCAN_NB ((Nn + SCAN_B - 1) / SCAN_B)   // 98

// Scratch (static __device__ — no allocs allowed)
__device__ float g_deg[Nn];
__device__ float g_dinv[Nn];
__device__ float g_xw[(size_t)Nn * Hh];
__device__ float g_h[(size_t)Nn * Hh];
__device__ float g_pool[Gg * Hh];
__device__ float g_cnt[Gg];

// CSR scratch
__device__ int    g_count[Nn];
__device__ int    g_cursor[Nn];
__device__ int    g_scan[Nn];
__device__ int    g_bsum[SCAN_NB];
__device__ int    g_boff[SCAN_NB];
__device__ int    g_rowptr[Nn + 1];
__device__ float2 g_csr[Ee];        // .x = src index (int bits), .y = coef

// precomputed bf16 split of W1/W2, transposed to [n][k] (contiguous k)
__device__ __nv_bfloat16 g_wth[2][128 * 128];
__device__ __nv_bfloat16 g_wtl[2][128 * 128];

// ---------------- helpers ----------------

__device__ __forceinline__ uint32_t smem_u32(const void* p) {
    uint32_t a;
    asm("{ .reg .u64 t; cvta.to.shared.u64 t, %1; cvt.u32.u64 %0, t; }"
        : "=r"(a) : "l"(p));
    return a;
}

#define LDMATRIX_X4(r0, r1, r2, r3, addr) \
    asm volatile("ldmatrix.sync.aligned.m8n8.x4.shared.b16 {%0,%1,%2,%3}, [%4];" \
                 : "=r"(r0), "=r"(r1), "=r"(r2), "=r"(r3) : "r"(addr))

#define MMA_BF16(c, a0, a1, a2, a3, b0, b1) \
    asm volatile("mma.sync.aligned.m16n8k16.row.col.f32.bf16.bf16.f32 " \
                 "{%0,%1,%2,%3}, {%4,%5,%6,%7}, {%8,%9}, {%0,%1,%2,%3};" \
                 : "+f"((c)[0]), "+f"((c)[1]), "+f"((c)[2]), "+f"((c)[3]) \
                 : "r"(a0), "r"(a1), "r"(a2), "r"(a3), "r"(b0), "r"(b1))

__device__ __forceinline__ uint32_t pack_bf16x2(__nv_bfloat16 lo, __nv_bfloat16 hi) {
    __nv_bfloat162 p(lo, hi);
    return *(uint32_t*)&p;
}

// 256B-row XOR swizzle: rows of 128 bf16; 16B chunk index XOR (row & 7).
// Conflict-free for ldmatrix (8 consecutive rows, same logical chunk ->
// 8 distinct chunk groups) and for linear fills.
__device__ __forceinline__ uint32_t swz(uint32_t row, uint32_t bytecol) {
    uint32_t chunk = bytecol >> 4;
    return row * 256u + (((chunk ^ (row & 7u)) << 4) | (bytecol & 15u));
}

// ---------------- W split: Wt_hi/lo[n][k] = split(W[k][n]) ----------------

__global__ void w_split_kernel(const float* __restrict__ W1,
                               const float* __restrict__ W2) {
    int idx = blockIdx.x * blockDim.x + threadIdx.x;   // 32768 total
    if (idx >= 2 * 128 * 128) return;
    int layer = idx >> 14;
    int n = (idx >> 7) & 127;
    int k = idx & 127;
    const float* W = layer ? W2 : W1;
    float w = W[(size_t)k * 128 + n];
    __nv_bfloat16 hw = __float2bfloat16_rn(w);
    g_wth[layer][n * 128 + k] = hw;
    g_wtl[layer][n * 128 + k] = __float2bfloat16_rn(w - __bfloat162float(hw));
}

// ---------------- tensor-core GEMM via mma.sync ----------------------------
// g_xw[n,128] = src[n,128] @ W[128,128]; src = A or g_h when A==nullptr.
// bf16 split x=hi+lo; acc = hi*Whi + hi*Wlo + lo*Whi (fp32 accum).
// Block tile 64x128, 8 warps: warp w -> rows (w&3)*16, cols (w>>2)*64.
// Swizzled smem, no padding: A 2x16KB + B 2x32KB = 96KB -> 2 CTAs/SM.

#define SM_AH 0
#define SM_AL (SM_AH + 16384)
#define SM_BH (SM_AL + 16384)
#define SM_BL (SM_BH + 32768)
#define SM_GEMM_TOTAL (SM_BL + 32768)   // 98304

__global__ void __launch_bounds__(256, 2)
gemm_mma_kernel(const float* __restrict__ A, int layer, int n) {
    extern __shared__ char smem[];
    const float* src = A ? A : (const float*)g_h;
    const uint32_t sb = smem_u32(smem);
    const int tid = threadIdx.x;
    const int wid = tid >> 5;
    const int lid = tid & 31;
    const int block_row = blockIdx.x * 64;

    // ---- fill A tile (hi/lo bf16, swizzled) ----
    for (int i = tid; i < 2048; i += 256) {        // 64 rows x 32 float4
        int r = i >> 5;
        int cq = i & 31;                            // float4 idx; cols cq*4
        int gr = block_row + r;
        float4 v = make_float4(0.f, 0.f, 0.f, 0.f);
        if (gr < n) v = ((const float4*)src)[(size_t)gr * 32 + cq];

        __nv_bfloat16 h0 = __float2bfloat16_rn(v.x);
        __nv_bfloat16 h1 = __float2bfloat16_rn(v.y);
        __nv_bfloat16 h2 = __float2bfloat16_rn(v.z);
        __nv_bfloat16 h3 = __float2bfloat16_rn(v.w);
        __nv_bfloat16 l0 = __float2bfloat16_rn(v.x - __bfloat162float(h0));
        __nv_bfloat16 l1 = __float2bfloat16_rn(v.y - __bfloat162float(h1));
        __nv_bfloat16 l2 = __float2bfloat16_rn(v.z - __bfloat162float(h2));
        __nv_bfloat16 l3 = __float2bfloat16_rn(v.w - __bfloat162float(h3));

        uint32_t off = swz((uint32_t)r, (uint32_t)cq * 8);   // 8B per float4
        *(uint2*)(smem + SM_AH + off) = make_uint2(pack_bf16x2(h0, h1), pack_bf16x2(h2, h3));
        *(uint2*)(smem + SM_AL + off) = make_uint2(pack_bf16x2(l0, l1), pack_bf16x2(l2, l3));
    }

    // ---- fill B tiles: straight copy of precomputed Wt (bf16), swizzled ----
    {
        const uint4* wh = (const uint4*)g_wth[layer];
        const uint4* wl = (const uint4*)g_wtl[layer];
        for (int i = tid; i < 2048; i += 256) {    // 128 rows x 16 uint4
            int r = i >> 4;
            int ch = i & 15;
            uint32_t off = swz((uint32_t)r, (uint32_t)ch * 16);
            *(uint4*)(smem + SM_BH + off) = wh[i];
            *(uint4*)(smem + SM_BL + off) = wl[i];
        }
    }
    __syncthreads();

    // ---- mma mainloop ----
    const int m0 = (wid & 3) * 16;
    const int c0 = (wid >> 2) * 64;
    float acc[4][2][4];
#pragma unroll
    for (int np = 0; np < 4; np++)
#pragma unroll
        for (int h = 0; h < 2; h++)
#pragma unroll
            for (int j = 0; j < 4; j++) acc[np][h][j] = 0.0f;

    const int lgrp = lid >> 3;
    const int lrow = lid & 7;
    const uint32_t a_row = (uint32_t)(m0 + ((lgrp & 1) << 3) + lrow);
    const uint32_t a_colb = (uint32_t)((lgrp >> 1) << 4);     // (lgrp>>1)*8 cols *2B
    const uint32_t b_rowbase = (uint32_t)(c0 + ((lgrp >> 1) << 3) + lrow);
    const uint32_t b_colb = (uint32_t)((lgrp & 1) << 4);      // (lgrp&1)*8 cols *2B

#pragma unroll
    for (int pass = 0; pass < 3; pass++) {
        const uint32_t abase = sb + ((pass == 2) ? SM_AL : SM_AH);
        const uint32_t bbase = sb + ((pass == 1) ? SM_BL : SM_BH);
#pragma unroll
        for (int kc = 0; kc < 8; kc++) {
            uint32_t a0, a1, a2, a3;
            LDMATRIX_X4(a0, a1, a2, a3, abase + swz(a_row, kc * 32 + a_colb));
#pragma unroll
            for (int np = 0; np < 4; np++) {
                uint32_t b0, b1, b2, b3;
                LDMATRIX_X4(b0, b1, b2, b3,
                            bbase + swz(b_rowbase + np * 16, kc * 32 + b_colb));
                MMA_BF16(acc[np][0], a0, a1, a2, a3, b0, b1);
                MMA_BF16(acc[np][1], a0, a1, a2, a3, b2, b3);
            }
        }
    }

    // ---- epilogue: write fp32 results ----
    {
        int r0 = block_row + m0 + (lid >> 2);
        int cb = (lid & 3) * 2;
#pragma unroll
        for (int np = 0; np < 4; np++) {
#pragma unroll
            for (int h = 0; h < 2; h++) {
                int col = c0 + np * 16 + h * 8 + cb;
                if (r0 < n)
                    *(float2*)(g_xw + (size_t)r0 * 128 + col) =
                        make_float2(acc[np][h][0], acc[np][h][1]);
                if (r0 + 8 < n)
                    *(float2*)(g_xw + (size_t)(r0 + 8) * 128 + col) =
                        make_float2(acc[np][h][2], acc[np][h][3]);
            }
        }
    }
}

// ---------------- init ----------------

__global__ void init_node_kernel() {
    int i = blockIdx.x * blockDim.x + threadIdx.x;
    if (i < Nn) {
        g_deg[i] = 1.0f;   // self-loop weight 1
        g_count[i] = 0;
        g_cursor[i] = 0;
    }
    if (i < Gg * Hh) g_pool[i] = 0.0f;
    if (i < Gg) g_cnt[i] = 0.0f;
}

__global__ void deg_count_kernel(const int* __restrict__ col,
                                 const float* __restrict__ ew) {
    int e = blockIdx.x * blockDim.x + threadIdx.x;
    if (e < Ee) {
        int c = col[e];
        atomicAdd(&g_deg[c], ew[e]);
        atomicAdd(&g_count[c], 1);
    }
}

// ---------------- scan ----------------

__global__ void scan_block_kernel() {
    __shared__ int sh[SCAN_B];
    int tid = threadIdx.x;
    int i = blockIdx.x * SCAN_B + tid;
    if (i < Nn) {
        float d = g_deg[i];
        g_dinv[i] = (d > 0.0f) ? rsqrtf(d) : 0.0f;
    }
    int v = (i < Nn) ? g_count[i] : 0;
    sh[tid] = v;
    __syncthreads();
#pragma unroll
    for (int o = 1; o < SCAN_B; o <<= 1) {
        int t = (tid >= o) ? sh[tid - o] : 0;
        __syncthreads();
        sh[tid] += t;
        __syncthreads();
    }
    if (i < Nn) g_scan[i] = sh[tid];
    if (tid == SCAN_B - 1) g_bsum[blockIdx.x] = sh[tid];
}

__global__ void scan_bsum_kernel() {
    __shared__ int sh[128];
    int tid = threadIdx.x;
    int v = (tid < SCAN_NB) ? g_bsum[tid] : 0;
    sh[tid] = v;
    __syncthreads();
#pragma unroll
    for (int o = 1; o < 128; o <<= 1) {
        int t = (tid >= o) ? sh[tid - o] : 0;
        __syncthreads();
        sh[tid] += t;
        __syncthreads();
    }
    if (tid < SCAN_NB) g_boff[tid] = sh[tid] - v;
}

__global__ void scan_final_kernel() {
    int i = blockIdx.x * blockDim.x + threadIdx.x;
    if (i < Nn) {
        g_rowptr[i + 1] = g_scan[i] + g_boff[i / SCAN_B];
        if (i == 0) g_rowptr[0] = 0;
    }
}

__global__ void csr_fill_kernel(const int* __restrict__ row,
                                const int* __restrict__ col,
                                const float* __restrict__ ew) {
    int e = blockIdx.x * blockDim.x + threadIdx.x;
    if (e >= Ee) return;
    int r = row[e];
    int c = col[e];
    int p = g_rowptr[c] + atomicAdd(&g_cursor[c], 1);
    g_csr[p] = make_float2(__int_as_float(r), g_dinv[r] * ew[e] * g_dinv[c]);
}

// ---------------- gather core: predicated x8 blocks ------------------------

__device__ __forceinline__ float4 gather_node(int node, int lane,
                                              const float* __restrict__ b) {
    const int start = g_rowptr[node];
    const int end = g_rowptr[node + 1];
    const int cnt = end - start;

    float di = g_dinv[node];
    float d2 = di * di;
    float4 sv = ((const float4*)(g_xw + (size_t)node * Hh))[lane];
    float ax = sv.x * d2, ay = sv.y * d2, az = sv.z * d2, aw = sv.w * d2;

#pragma unroll 1
    for (int blk = 0; blk < cnt; blk += 8) {
        float2 e[8];
        float cf[8];
#pragma unroll
        for (int u = 0; u < 8; u++) {
            int q = blk + u;
            int qs = (q < cnt) ? q : cnt - 1;
            e[u] = g_csr[start + qs];
            cf[u] = (q < cnt) ? e[u].y : 0.0f;
        }
        float4 v[8];
#pragma unroll
        for (int u = 0; u < 8; u++)
            v[u] = ((const float4*)(g_xw + (size_t)__float_as_int(e[u].x) * Hh))[lane];
#pragma unroll
        for (int u = 0; u < 8; u++) {
            ax += cf[u] * v[u].x;
            ay += cf[u] * v[u].y;
            az += cf[u] * v[u].z;
            aw += cf[u] * v[u].w;
        }
    }

    float4 bv = *(const float4*)(b + lane * 4);
    return make_float4(fmaxf(ax + bv.x, 0.0f), fmaxf(ay + bv.y, 0.0f),
                       fmaxf(az + bv.z, 0.0f), fmaxf(aw + bv.w, 0.0f));
}

__global__ void gather1_kernel(const float* __restrict__ b) {
    int node = blockIdx.x * 8 + (threadIdx.x >> 5);
    if (node >= Nn) return;
    int lane = threadIdx.x & 31;
    float4 acc = gather_node(node, lane, b);
    ((float4*)(g_h + (size_t)node * Hh))[lane] = acc;
}

__global__ void gather2_pool_kernel(const float* __restrict__ b,
                                    const int* __restrict__ batch) {
    int node = blockIdx.x * 8 + (threadIdx.x >> 5);
    if (node >= Nn) return;
    int lane = threadIdx.x & 31;
    float4 acc = gather_node(node, lane, b);
    int bg = batch[node];
    float* pl = g_pool + bg * Hh + lane * 4;
    atomicAdd(pl + 0, acc.x);
    atomicAdd(pl + 1, acc.y);
    atomicAdd(pl + 2, acc.z);
    atomicAdd(pl + 3, acc.w);
    if (lane == 0) atomicAdd(&g_cnt[bg], 1.0f);
}

// ---------------- final FC ----------------

__global__ void fc_kernel(float* __restrict__ out,
                          const float* __restrict__ Wfc,
                          const float* __restrict__ bfc) {
    int g = threadIdx.x >> 4;
    int o = threadIdx.x & 15;
    float inv = 1.0f / fmaxf(g_cnt[g], 1.0f);
    float acc = 0.0f;
#pragma unroll 8
    for (int k = 0; k < Hh; k++) acc += g_pool[g * Hh + k] * Wfc[k * Oo + o];
    out[g * Oo + o] = acc * inv + bfc[o];
}

// ---------------- launch ----------------

extern "C" void kernel_launch(void* const* d_in, const int* in_sizes, int n_in,
                              void* d_out, int out_size) {
    const float* x = (const float*)d_in[0];
    const int* edge_index = (const int*)d_in[1];   // int32
    const float* ew = (const float*)d_in[2];
    const int* batch = (const int*)d_in[3];        // int32
    const float* W1 = (const float*)d_in[4];
    const float* b1 = (const float*)d_in[5];
    const float* W2 = (const float*)d_in[6];
    const float* b2 = (const float*)d_in[7];
    const float* Wfc = (const float*)d_in[8];
    const float* bfc = (const float*)d_in[9];
    float* out = (float*)d_out;

    const int* row = edge_index;        // edge_index[0]
    const int* col = edge_index + Ee;   // edge_index[1]

    const int nblk = (Nn + 255) / 256;
    const int eblk = (Ee + 255) / 256;
    const int gemm_blocks = (Nn + 63) / 64;     // 782
    const int warp8_blocks = (Nn + 7) / 8;

    cudaFuncSetAttribute(gemm_mma_kernel,
                         cudaFuncAttributeMaxDynamicSharedMemorySize, SM_GEMM_TOTAL);

    // degree + CSR build (+ one-time W bf16 split)
    init_node_kernel<<<nblk, 256>>>();
    w_split_kernel<<<(2 * 128 * 128 + 255) / 256, 256>>>(W1, W2);
    deg_count_kernel<<<eblk, 256>>>(col, ew);
    scan_block_kernel<<<SCAN_NB, SCAN_B>>>();   // also computes dinv
    scan_bsum_kernel<<<1, 128>>>();
    scan_final_kernel<<<nblk, 256>>>();
    csr_fill_kernel<<<eblk, 256>>>(row, col, ew);

    // layer 1: xw = x@W1 ; h = relu(gather(xw) + dinv^2*xw + b1)
    gemm_mma_kernel<<<gemm_blocks, 256, SM_GEMM_TOTAL>>>(x, 0, Nn);
    gather1_kernel<<<warp8_blocks, 256>>>(b1);

    // layer 2: xw = h@W2 ; pooled gather (no h2 materialization)
    gemm_mma_kernel<<<gemm_blocks, 256, SM_GEMM_TOTAL>>>(nullptr, 1, Nn);
    gather2_pool_kernel<<<warp8_blocks, 256>>>(b2, batch);

    // fc
    fc_kernel<<<1, Gg * Oo>>>(out, Wfc, bfc);
}